// round 10
// baseline (speedup 1.0000x reference)
#include <cuda_runtime.h>
#include <cstdint>

// Shapes (fixed by setup_inputs):
//   k_cache: (B=4, H=8, D=128, 128, 64) f32 -> (BH=32, D=128, SFULL=8192)
//   v_cache: (B=4, H=8, 128, 64, D=128) f32 -> (BH=32, SFULL=8192, D=128)
//   S = 6144 (derived from out_size)
// out = stack([transpose_k(:, :, :S), v(:, :S, :)]) -> (2, BH, S, D)

#define BH_     32
#define BH_SM_  16     // V for bh < 16 handled by SM kernel; bh >= 16 by CE
#define D_      128
#define SFULL_  8192

// SM kernel (R2 body, proven 78% DRAM):
//   blocks [0, 2*BH_SM_*tiles): interleaved K/V for bh 0..15 (even=K, odd=V)
//   blocks [2*BH_SM_*tiles, 3*BH_SM_*tiles): K-only for bh 16..31
__global__ __launch_bounds__(256, 8) void fused_kv_kernel(
    const float*  __restrict__ kin,
    const float4* __restrict__ vin,
    float*        __restrict__ outk,
    float4*       __restrict__ outv,
    int S, int tilesPerBh)
{
    const int b = blockIdx.x;
    const int t = threadIdx.x;

    int bh, jj;
    bool isV;
    if (b < 2 * BH_SM_ * tilesPerBh) {
        isV = (b & 1);
        const int id = b >> 1;
        bh = id / tilesPerBh;
        jj = id - bh * tilesPerBh;            // bh in [0,16)
    } else {
        isV = false;
        const int id = b - BH_SM_ * tilesPerBh;   // maps to bh in [16,32)
        bh = id / tilesPerBh;
        jj = id - bh * tilesPerBh;
    }

    if (isV) {
        // ------------------ V copy: contiguous 16 KB chunk ------------------
        const float4* src = vin  + (size_t)bh * (SFULL_ * (D_ / 4)) + (size_t)jj * 1024;
        float4*       dst = outv + (size_t)bh * ((size_t)S * (D_ / 4)) + (size_t)jj * 1024;

        float4 v0 = src[t];
        float4 v1 = src[t + 256];
        float4 v2 = src[t + 512];
        float4 v3 = src[t + 768];
        dst[t]       = v0;
        dst[t + 256] = v1;
        dst[t + 512] = v2;
        dst[t + 768] = v3;
    } else {
        // --------------- K transpose: (D=128, s=32) -> (s=32, D=128) --------
        // tile[s][d], row stride 129 floats:
        //   STS bank = (4f+k+d) mod 32  -> conflict-free per warp
        //   LDS bank = (s+d)    mod 32  -> conflict-free per warp
        __shared__ float tile[32][129];

        const int s0 = jj * 32;
        const float* src = kin  + (size_t)bh * D_ * SFULL_ + s0;
        float*       dst = outk + (size_t)bh * (size_t)S * D_ + (size_t)s0 * D_;

        float4 r[4];
#pragma unroll
        for (int i = 0; i < 4; ++i) {
            const int idx = t + i * 256;
            const int d = idx >> 3;       // 0..127
            const int f = idx & 7;        // float4 index along s
            r[i] = *(const float4*)(src + (size_t)d * SFULL_ + 4 * f);
        }
#pragma unroll
        for (int i = 0; i < 4; ++i) {
            const int idx = t + i * 256;
            const int d = idx >> 3;
            const int f = idx & 7;
            tile[4 * f + 0][d] = r[i].x;
            tile[4 * f + 1][d] = r[i].y;
            tile[4 * f + 2][d] = r[i].z;
            tile[4 * f + 3][d] = r[i].w;
        }
        __syncthreads();

        // Drain: each warp writes a contiguous 128 B segment; block writes a
        // fully contiguous 16 KB output region.
#pragma unroll
        for (int i = 0; i < 16; ++i) {
            const int e = t + i * 256;
            const int s = e >> 7;
            const int d = e & 127;
            dst[(size_t)s * D_ + d] = tile[s][d];
        }
    }
}

extern "C" void kernel_launch(void* const* d_in, const int* in_sizes, int n_in,
                              void* d_out, int out_size) {
    const float* k_cache = (const float*)d_in[0];
    const float* v_cache = (const float*)d_in[1];
    // seq_len fully determined by out_size: out = 2 * BH * S * D elems.
    const int S = out_size / (2 * BH_ * D_);        // 6144
    const int tilesPerBh = S / 32;                  // 192

    float*  out_k = (float*)d_out;                                  // (BH,S,D)
    float*  out_v = (float*)d_out + (size_t)BH_ * S * D_;

    // Fork a side stream inside capture for the CE branch (V back half).
    // Stream/events are created per call and intentionally leaked: host-side
    // resources only, kernel_launch runs O(1) times; no device memory alloc.
    cudaStream_t s2;
    cudaEvent_t  eFork, eJoin;
    cudaStreamCreateWithFlags(&s2, cudaStreamNonBlocking);
    cudaEventCreateWithFlags(&eFork, cudaEventDisableTiming);
    cudaEventCreateWithFlags(&eJoin, cudaEventDisableTiming);

    cudaEventRecord(eFork, 0);
    cudaStreamWaitEvent(s2, eFork, 0);

    // CE branch: V rows for bh 16..31 — strided 2D block copy.
    {
        const char*  src    = (const char*)v_cache
                            + (size_t)BH_SM_ * SFULL_ * D_ * sizeof(float);
        char*        dst    = (char*)out_v
                            + (size_t)BH_SM_ * S * D_ * sizeof(float);
        const size_t spitch = (size_t)SFULL_ * D_ * sizeof(float);   // 4 MB
        const size_t width  = (size_t)S * D_ * sizeof(float);        // 3 MB
        cudaMemcpy2DAsync(dst, width, src, spitch, width,
                          BH_ - BH_SM_, cudaMemcpyDeviceToDevice, s2);
    }
    cudaEventRecord(eJoin, s2);

    // SM branch: K (all bh) + V front half. Runs concurrently with the CE copy.
    {
        dim3 block(256, 1, 1);
        dim3 grid((unsigned)(3 * BH_SM_ * tilesPerBh), 1, 1);        // 9216
        fused_kv_kernel<<<grid, block>>>(k_cache, (const float4*)v_cache,
                                         out_k, (float4*)out_v, S, tilesPerBh);
    }

    // Join: downstream (harness end-of-capture) depends on both branches.
    cudaStreamWaitEvent(0, eJoin, 0);
}

// round 11
// speedup vs baseline: 1.5375x; 1.5375x over previous
#include <cuda_runtime.h>
#include <cstdint>

// Shapes (fixed by setup_inputs):
//   k_cache: (B=4, H=8, D=128, 128, 64) f32 -> (BH=32, D=128, SFULL=8192)
//   v_cache: (B=4, H=8, 128, 64, D=128) f32 -> (BH=32, SFULL=8192, D=128)
//   S = 6144 (derived from out_size)
// out = stack([transpose_k(:, :, :S), v(:, :S, :)]) -> (2, BH, S, D)
//
// Final converged kernel (best of 10 measured variants):
//   - interleaved independent 16 KB blocks (even = K-transpose, odd = V-copy)
//   - 8 CTAs/SM, 32 regs, 17 KB smem
//   - conflict-free [32][129] tile: STS banks (4f+k+d)%32 and LDS banks
//     (s+d)%32 each cover all 32 banks exactly once per warp
//   - every GMEM access is a full 128 B coalesced warp segment; each K block
//     writes a fully contiguous 16 KB output region
// Measured: kernel 56.3 us @ 6.21 TB/s (78.4% DRAM) — mixed R/W HBM wall.

#define BH_    32
#define D_     128
#define SFULL_ 8192

__global__ __launch_bounds__(256) void fused_kv_kernel(
    const float*  __restrict__ kin,
    const float4* __restrict__ vin,
    float*        __restrict__ outk,
    float4*       __restrict__ outv,
    int S, int tilesPerBh)
{
    const int b  = blockIdx.x;
    const int t  = threadIdx.x;
    const int id = b >> 1;
    const int bh = id / tilesPerBh;
    const int jj = id - bh * tilesPerBh;

    if (b & 1) {
        // ------------------ V copy: contiguous 16 KB chunk ------------------
        const float4* src = vin  + (size_t)bh * (SFULL_ * (D_ / 4)) + (size_t)jj * 1024;
        float4*       dst = outv + (size_t)bh * ((size_t)S * (D_ / 4)) + (size_t)jj * 1024;
#pragma unroll
        for (int i = 0; i < 4; ++i)
            dst[t + i * 256] = src[t + i * 256];
    } else {
        // --------------- K transpose: (D=128, s=32) -> (s=32, D=128) --------
        __shared__ float tile[32][129];

        const int s0 = jj * 32;
        const float* src = kin  + (size_t)bh * D_ * SFULL_ + s0;
        float*       dst = outk + (size_t)bh * (size_t)S * D_ + (size_t)s0 * D_;

        // Load: 1024 float4; each 8-lane group reads a contiguous 128 B of
        // one d-row (coalesced), 4-deep MLP per thread.
#pragma unroll
        for (int i = 0; i < 4; ++i) {
            const int idx = t + i * 256;
            const int d = idx >> 3;       // 0..127
            const int f = idx & 7;        // float4 index along s
            float4 val = *(const float4*)(src + (size_t)d * SFULL_ + 4 * f);
            tile[4 * f + 0][d] = val.x;
            tile[4 * f + 1][d] = val.y;
            tile[4 * f + 2][d] = val.z;
            tile[4 * f + 3][d] = val.w;
        }
        __syncthreads();

        // Drain: each warp writes a contiguous 128 B segment; the block
        // writes a fully contiguous 16 KB region of the output.
#pragma unroll
        for (int i = 0; i < 16; ++i) {
            const int e = t + i * 256;
            const int s = e >> 7;         // 0..31
            const int d = e & 127;        // 0..127
            dst[(size_t)s * D_ + d] = tile[s][d];
        }
    }
}

extern "C" void kernel_launch(void* const* d_in, const int* in_sizes, int n_in,
                              void* d_out, int out_size) {
    const float* k_cache = (const float*)d_in[0];
    const float* v_cache = (const float*)d_in[1];
    // seq_len is fully determined by out_size: out = 2 * BH * S * D elems.
    const int S = out_size / (2 * BH_ * D_);        // 6144
    const int tilesPerBh = S / 32;                  // 192

    float*  out_k = (float*)d_out;                                  // (BH,S,D)
    float4* out_v = (float4*)((float*)d_out + (size_t)BH_ * S * D_);

    dim3 block(256, 1, 1);
    dim3 grid((unsigned)(2 * BH_ * tilesPerBh), 1, 1);              // 12288
    fused_kv_kernel<<<grid, block>>>(k_cache, (const float4*)v_cache,
                                     out_k, out_v, S, tilesPerBh);
}